// round 1
// baseline (speedup 1.0000x reference)
#include <cuda_runtime.h>
#include <cstdint>
#include <cstddef>

// ---------------- problem dims ----------------
#define S_LEN  2048
#define BATCH  2
#define DMODEL 4096
#define NHQ    32
#define NKV    8
#define HDIM   128
#define N_QKV  ((NHQ + 2*NKV)*HDIM)   // 6144
#define MROWS  (S_LEN*BATCH)          // 4096

// ---------------- scratch (device globals; no allocs allowed) ----------------
__device__ float g_Q [(size_t)BATCH*NHQ*S_LEN*HDIM];   // [B][NH][S][HD]
__device__ float g_Kt[(size_t)BATCH*NKV*HDIM*S_LEN];   // [B][NKV][HD][S]  (d-major!)
__device__ float g_V [(size_t)BATCH*NKV*S_LEN*HDIM];   // [B][NKV][S][HD]
__device__ float g_attn[(size_t)MROWS*NHQ*HDIM];       // [S*B][NH*HD]

// ---------------- small helpers ----------------
__device__ __forceinline__ uint32_t f2tf(float f) {
    uint32_t r; asm("cvt.rna.tf32.f32 %0, %1;" : "=r"(r) : "f"(f)); return r;
}
__device__ __forceinline__ void mma_tf32(float* c, const uint32_t* a, const uint32_t* b) {
    asm volatile(
        "mma.sync.aligned.m16n8k8.row.col.f32.tf32.tf32.f32 "
        "{%0,%1,%2,%3},{%4,%5,%6,%7},{%8,%9},{%0,%1,%2,%3};"
        : "+f"(c[0]), "+f"(c[1]), "+f"(c[2]), "+f"(c[3])
        : "r"(a[0]), "r"(a[1]), "r"(a[2]), "r"(a[3]), "r"(b[0]), "r"(b[1]));
}
__device__ __forceinline__ uint32_t s2u(const void* p) {
    return (uint32_t)__cvta_generic_to_shared(p);
}
__device__ __forceinline__ void cp16(uint32_t s, const void* g) {
    asm volatile("cp.async.cg.shared.global [%0], [%1], 16;" :: "r"(s), "l"(g));
}
__device__ __forceinline__ void cp_commit() { asm volatile("cp.async.commit_group;"); }
__device__ __forceinline__ void cp_wait0()  { asm volatile("cp.async.wait_group 0;"); }

#define NEG_INF __int_as_float(0xff800000)

// =====================================================================
// GEMM: C[M,N] = A[M,K] * W[K,N], tf32 mma, 128x128x32 tiles, 8 warps.
// MODE 0: A = hidden (param), W = w_qkv, scatter epilogue -> g_Q/g_Kt/g_V
// MODE 1: A = g_attn,         W = w_o,   plain epilogue   -> C (param)
// =====================================================================
#define BM 128
#define BN 128
#define BK 32
#define AS_STRIDE 36    // 128*36 floats per buffer; bank(4*gid+tig) conflict-free
#define BS_STRIDE 136   // 32*136 floats per buffer; bank(8*tig+gid) conflict-free
#define GEMM_SMEM (2*(BM*AS_STRIDE + BK*BS_STRIDE)*4)   // 71680 B

__device__ __forceinline__ void qkv_store(int r, int n, float v) {
    int s = r >> 1, b = r & 1;
    int d = n & 127;
    if (n < NHQ*HDIM) {
        int h = n >> 7;
        g_Q[(((size_t)b*NHQ + h)*S_LEN + s)*HDIM + d] = v;
    } else if (n < (NHQ+NKV)*HDIM) {
        int h = (n - NHQ*HDIM) >> 7;
        g_Kt[(((size_t)b*NKV + h)*HDIM + d)*S_LEN + s] = v;
    } else {
        int h = (n - (NHQ+NKV)*HDIM) >> 7;
        g_V[(((size_t)b*NKV + h)*S_LEN + s)*HDIM + d] = v;
    }
}

template<int MODE>
__global__ __launch_bounds__(256, 2)
void gemm_tf32_kernel(const float* __restrict__ A,
                      const float* __restrict__ W,
                      float* __restrict__ C) {
    constexpr int N = (MODE == 0) ? N_QKV : DMODEL;
    constexpr int K = DMODEL;
    constexpr int KT = K / BK;   // 128

    extern __shared__ float sm[];
    float* As = sm;                         // [2][BM][AS_STRIDE]
    float* Bs = sm + 2*BM*AS_STRIDE;        // [2][BK][BS_STRIDE]

    const int tid  = threadIdx.x;
    const int wid  = tid >> 5, lane = tid & 31;
    const int gid  = lane >> 2, tig = lane & 3;
    const int wrow = wid >> 1, wcol = wid & 1;    // warp tile: 32 rows x 64 cols
    const int bn   = blockIdx.x, bm = blockIdx.y;

    const float* Ag = (MODE == 1) ? g_attn : A;

    auto loadA = [&](int buf, int k0) {
        float* dst = As + buf*BM*AS_STRIDE;
        #pragma unroll
        for (int p = 0; p < 4; p++) {
            int j = tid + p*256;
            int row = j >> 3, ch = j & 7;            // 128 rows x 8 chunks(16B)
            cp16(s2u(dst + row*AS_STRIDE + ch*4),
                 Ag + (size_t)(bm*BM + row)*K + k0 + ch*4);
        }
    };
    auto loadB = [&](int buf, int k0) {
        float* dst = Bs + buf*BK*BS_STRIDE;
        #pragma unroll
        for (int p = 0; p < 4; p++) {
            int j = tid + p*256;
            int row = j >> 5, ch = j & 31;           // 32 rows x 32 chunks(16B)
            cp16(s2u(dst + row*BS_STRIDE + ch*4),
                 W + (size_t)(k0 + row)*N + bn*BN + ch*4);
        }
    };

    float acc[2][8][4];
    #pragma unroll
    for (int mf = 0; mf < 2; mf++)
        #pragma unroll
        for (int nf = 0; nf < 8; nf++)
            #pragma unroll
            for (int i = 0; i < 4; i++) acc[mf][nf][i] = 0.f;

    loadA(0, 0); loadB(0, 0); cp_commit();

    for (int kt = 0; kt < KT; kt++) {
        cp_wait0();
        __syncthreads();
        if (kt + 1 < KT) {
            loadA((kt+1)&1, (kt+1)*BK);
            loadB((kt+1)&1, (kt+1)*BK);
            cp_commit();
        }
        const float* a = As + (kt&1)*BM*AS_STRIDE;
        const float* b = Bs + (kt&1)*BK*BS_STRIDE;

        #pragma unroll
        for (int ks = 0; ks < 4; ks++) {
            uint32_t af[2][4];
            #pragma unroll
            for (int mf = 0; mf < 2; mf++) {
                int r = wrow*32 + mf*16 + gid;
                int c = ks*8 + tig;
                af[mf][0] = f2tf(a[r*AS_STRIDE + c]);
                af[mf][1] = f2tf(a[(r+8)*AS_STRIDE + c]);
                af[mf][2] = f2tf(a[r*AS_STRIDE + c + 4]);
                af[mf][3] = f2tf(a[(r+8)*AS_STRIDE + c + 4]);
            }
            #pragma unroll
            for (int nf = 0; nf < 8; nf++) {
                uint32_t bf[2];
                int cc = wcol*64 + nf*8 + gid;
                int rr = ks*8 + tig;
                bf[0] = f2tf(b[rr*BS_STRIDE + cc]);
                bf[1] = f2tf(b[(rr+4)*BS_STRIDE + cc]);
                mma_tf32(acc[0][nf], af[0], bf);
                mma_tf32(acc[1][nf], af[1], bf);
            }
        }
        __syncthreads();
    }

    // epilogue
    #pragma unroll
    for (int mf = 0; mf < 2; mf++) {
        #pragma unroll
        for (int nf = 0; nf < 8; nf++) {
            int r = bm*BM + wrow*32 + mf*16 + gid;
            int c = bn*BN + wcol*64 + nf*8 + tig*2;
            float v0 = acc[mf][nf][0], v1 = acc[mf][nf][1];
            float v2 = acc[mf][nf][2], v3 = acc[mf][nf][3];
            if (MODE == 1) {
                C[(size_t)r*N + c]       = v0;
                C[(size_t)r*N + c + 1]   = v1;
                C[(size_t)(r+8)*N + c]   = v2;
                C[(size_t)(r+8)*N + c+1] = v3;
            } else {
                qkv_store(r,   c,   v0);
                qkv_store(r,   c+1, v1);
                qkv_store(r+8, c,   v2);
                qkv_store(r+8, c+1, v3);
            }
        }
    }
}

// =====================================================================
// Flash attention: block = (qtile 128 rows, head h, batch b).
// 8 warps, each owns 16 query rows -> softmax is warp-local.
// KV tiles of 64, cp.async double-buffered.
// =====================================================================
#define BKV 64
#define KS_STRIDE 72     // K tile [d=128][kv=64] + pad; bank(8*tig+gid) OK
#define VS_STRIDE 136    // V tile [kv=64][d=128] + pad; bank(8*tig+gid) OK
#define ATTN_SMEM (2*(HDIM*KS_STRIDE + BKV*VS_STRIDE)*4)   // 143360 B

__global__ __launch_bounds__(256, 1)
void attn_kernel() {
    extern __shared__ float sm[];
    float* Ks = sm;                       // [2][128][KS_STRIDE]
    float* Vs = sm + 2*HDIM*KS_STRIDE;    // [2][64][VS_STRIDE]

    const int tid = threadIdx.x;
    const int wid = tid >> 5, lane = tid & 31;
    const int gid = lane >> 2, tig = lane & 3;
    const int qt = blockIdx.x, h = blockIdx.y, b = blockIdx.z;
    const int hk = h >> 2;   // GQA: 4 q heads per kv head
    const float scale = 0.08838834764831845f;   // 1/sqrt(128)

    // ---- Q fragments straight from global (one-time), scale folded in ----
    const float* Qg = g_Q + (((size_t)b*NHQ + h)*S_LEN + qt*128 + wid*16)*HDIM;
    uint32_t qa[16][4];
    #pragma unroll
    for (int kk = 0; kk < 16; kk++) {
        int c = kk*8 + tig;
        qa[kk][0] = f2tf(Qg[(size_t)gid*HDIM + c] * scale);
        qa[kk][1] = f2tf(Qg[(size_t)(gid+8)*HDIM + c] * scale);
        qa[kk][2] = f2tf(Qg[(size_t)gid*HDIM + c + 4] * scale);
        qa[kk][3] = f2tf(Qg[(size_t)(gid+8)*HDIM + c + 4] * scale);
    }

    const float* Kg = g_Kt + ((size_t)b*NKV + hk)*HDIM*S_LEN;   // [d][s]
    const float* Vg = g_V  + ((size_t)b*NKV + hk)*S_LEN*HDIM;   // [s][d]

    auto loadKV = [&](int buf, int it) {
        float* kd = Ks + buf*HDIM*KS_STRIDE;
        #pragma unroll
        for (int p = 0; p < 8; p++) {
            int j = tid + p*256;
            int d = j >> 4, ch = j & 15;             // 128 rows x 16 chunks
            cp16(s2u(kd + d*KS_STRIDE + ch*4),
                 Kg + (size_t)d*S_LEN + it*BKV + ch*4);
        }
        float* vd = Vs + buf*BKV*VS_STRIDE;
        #pragma unroll
        for (int p = 0; p < 8; p++) {
            int j = tid + p*256;
            int r = j >> 5, ch = j & 31;             // 64 rows x 32 chunks
            cp16(s2u(vd + r*VS_STRIDE + ch*4),
                 Vg + (size_t)(it*BKV + r)*HDIM + ch*4);
        }
    };

    float m0 = NEG_INF, m1 = NEG_INF, l0 = 0.f, l1 = 0.f;
    float o[16][4];
    #pragma unroll
    for (int jn = 0; jn < 16; jn++)
        #pragma unroll
        for (int i = 0; i < 4; i++) o[jn][i] = 0.f;

    loadKV(0, 0); cp_commit();

    const int NIT = S_LEN / BKV;   // 32
    for (int it = 0; it < NIT; it++) {
        cp_wait0();
        __syncthreads();
        if (it + 1 < NIT) { loadKV((it+1)&1, it+1); cp_commit(); }

        const float* kb = Ks + (it&1)*HDIM*KS_STRIDE;
        const float* vb = Vs + (it&1)*BKV*VS_STRIDE;

        // ---- S = (Q*scale) K^T : per warp 16 x 64 ----
        float sc[8][4];
        #pragma unroll
        for (int jn = 0; jn < 8; jn++)
            #pragma unroll
            for (int i = 0; i < 4; i++) sc[jn][i] = 0.f;

        #pragma unroll
        for (int ks = 0; ks < 16; ks++) {
            #pragma unroll
            for (int jn = 0; jn < 8; jn++) {
                uint32_t bf[2];
                int rr = ks*8 + tig, cc = jn*8 + gid;
                bf[0] = f2tf(kb[rr*KS_STRIDE + cc]);
                bf[1] = f2tf(kb[(rr+4)*KS_STRIDE + cc]);
                mma_tf32(sc[jn], qa[ks], bf);
            }
        }

        // ---- online softmax (rows gid and gid+8, quad-local reductions) ----
        float rmax0 = NEG_INF, rmax1 = NEG_INF;
        #pragma unroll
        for (int jn = 0; jn < 8; jn++) {
            rmax0 = fmaxf(rmax0, fmaxf(sc[jn][0], sc[jn][1]));
            rmax1 = fmaxf(rmax1, fmaxf(sc[jn][2], sc[jn][3]));
        }
        rmax0 = fmaxf(rmax0, __shfl_xor_sync(0xffffffffu, rmax0, 1));
        rmax0 = fmaxf(rmax0, __shfl_xor_sync(0xffffffffu, rmax0, 2));
        rmax1 = fmaxf(rmax1, __shfl_xor_sync(0xffffffffu, rmax1, 1));
        rmax1 = fmaxf(rmax1, __shfl_xor_sync(0xffffffffu, rmax1, 2));

        float mn0 = fmaxf(m0, rmax0), mn1 = fmaxf(m1, rmax1);
        float al0 = __expf(m0 - mn0), al1 = __expf(m1 - mn1);

        float rs0 = 0.f, rs1 = 0.f;
        #pragma unroll
        for (int jn = 0; jn < 8; jn++) {
            sc[jn][0] = __expf(sc[jn][0] - mn0);
            sc[jn][1] = __expf(sc[jn][1] - mn0);
            sc[jn][2] = __expf(sc[jn][2] - mn1);
            sc[jn][3] = __expf(sc[jn][3] - mn1);
            rs0 += sc[jn][0] + sc[jn][1];
            rs1 += sc[jn][2] + sc[jn][3];
        }
        rs0 += __shfl_xor_sync(0xffffffffu, rs0, 1);
        rs0 += __shfl_xor_sync(0xffffffffu, rs0, 2);
        rs1 += __shfl_xor_sync(0xffffffffu, rs1, 1);
        rs1 += __shfl_xor_sync(0xffffffffu, rs1, 2);

        l0 = l0*al0 + rs0;  l1 = l1*al1 + rs1;
        m0 = mn0;           m1 = mn1;

        #pragma unroll
        for (int jn = 0; jn < 16; jn++) {
            o[jn][0] *= al0; o[jn][1] *= al0;
            o[jn][2] *= al1; o[jn][3] *= al1;
        }

        // ---- O += P V : convert P (C-layout) -> A-layout via quad shuffles ----
        #pragma unroll
        for (int ks = 0; ks < 8; ks++) {
            int srcA = (lane & 28) + (tig >> 1);
            int srcB = srcA + 2;
            float x0 = __shfl_sync(0xffffffffu, sc[ks][0], srcA);
            float y0 = __shfl_sync(0xffffffffu, sc[ks][1], srcA);
            float x2 = __shfl_sync(0xffffffffu, sc[ks][2], srcA);
            float y2 = __shfl_sync(0xffffffffu, sc[ks][3], srcA);
            float u0 = __shfl_sync(0xffffffffu, sc[ks][0], srcB);
            float v0 = __shfl_sync(0xffffffffu, sc[ks][1], srcB);
            float u2 = __shfl_sync(0xffffffffu, sc[ks][2], srcB);
            float v2 = __shfl_sync(0xffffffffu, sc[ks][3], srcB);
            bool odd = (tig & 1);
            uint32_t pa[4];
            pa[0] = f2tf(odd ? y0 : x0);   // (row gid,   col tig)
            pa[1] = f2tf(odd ? y2 : x2);   // (row gid+8, col tig)
            pa[2] = f2tf(odd ? v0 : u0);   // (row gid,   col tig+4)
            pa[3] = f2tf(odd ? v2 : u2);   // (row gid+8, col tig+4)

            #pragma unroll
            for (int jn = 0; jn < 16; jn++) {
                uint32_t bf[2];
                int rr = ks*8 + tig, cc = jn*8 + gid;
                bf[0] = f2tf(vb[rr*VS_STRIDE + cc]);
                bf[1] = f2tf(vb[(rr+4)*VS_STRIDE + cc]);
                mma_tf32(o[jn], pa, bf);
            }
        }
    }

    // ---- epilogue: write [s*B+b][h*128+d] into g_attn ----
    float il0 = 1.f / l0, il1 = 1.f / l1;
    int s0 = qt*128 + wid*16 + gid;
    size_t r0 = (size_t)(s0*BATCH + b) * (NHQ*HDIM);
    size_t r1 = (size_t)((s0+8)*BATCH + b) * (NHQ*HDIM);
    #pragma unroll
    for (int jn = 0; jn < 16; jn++) {
        int c = h*HDIM + jn*8 + tig*2;
        g_attn[r0 + c]     = o[jn][0] * il0;
        g_attn[r0 + c + 1] = o[jn][1] * il0;
        g_attn[r1 + c]     = o[jn][2] * il1;
        g_attn[r1 + c + 1] = o[jn][3] * il1;
    }
}

// =====================================================================
// launcher
// =====================================================================
extern "C" void kernel_launch(void* const* d_in, const int* in_sizes, int n_in,
                              void* d_out, int out_size) {
    const float* hidden = (const float*)d_in[0];   // [S,B,D]
    const float* w_qkv  = (const float*)d_in[1];   // [D, 6144]
    const float* w_o    = (const float*)d_in[2];   // [4096, 4096]
    float* out = (float*)d_out;                    // [S,B,D]

    cudaFuncSetAttribute(gemm_tf32_kernel<0>,
                         cudaFuncAttributeMaxDynamicSharedMemorySize, GEMM_SMEM);
    cudaFuncSetAttribute(gemm_tf32_kernel<1>,
                         cudaFuncAttributeMaxDynamicSharedMemorySize, GEMM_SMEM);
    cudaFuncSetAttribute(attn_kernel,
                         cudaFuncAttributeMaxDynamicSharedMemorySize, ATTN_SMEM);

    // 1) fused QKV projection with scatter to Q / K^T / V layouts
    gemm_tf32_kernel<0><<<dim3(N_QKV/BN, MROWS/BM), 256, GEMM_SMEM>>>(hidden, w_qkv, nullptr);

    // 2) flash attention (full softmax == ring online-softmax)
    attn_kernel<<<dim3(S_LEN/128, NHQ, BATCH), 256, ATTN_SMEM>>>();

    // 3) output projection
    gemm_tf32_kernel<1><<<dim3(DMODEL/BN, MROWS/BM), 256, GEMM_SMEM>>>(nullptr, w_o, out);
}

// round 3
// speedup vs baseline: 1.2819x; 1.2819x over previous
#include <cuda_runtime.h>
#include <cstdint>
#include <cstddef>

// ---------------- problem dims ----------------
#define S_LEN  2048
#define BATCH  2
#define DMODEL 4096
#define NHQ    32
#define NKV    8
#define HDIM   128
#define N_QKV  ((NHQ + 2*NKV)*HDIM)   // 6144
#define MROWS  (S_LEN*BATCH)          // 4096
#define KG_ALL (DMODEL/8)             // 512

// ---------------- scratch (device globals; no allocs allowed) ----------------
// A-fragment layout: idx = ((mb*512 + kg)*32 + lane)*4 + v
__device__ float g_hid2 [(size_t)MROWS*DMODEL];
__device__ float g_attn2[(size_t)MROWS*DMODEL];
// W pair layout: idx = (kg*N + n)*8 + t2
__device__ float g_Wq2[(size_t)DMODEL*N_QKV];
__device__ float g_Wo2[(size_t)DMODEL*DMODEL];
// Q fragment layout: idx = (((bh*128 + sb)*16 + kk)*32 + lane)*4 + v
__device__ float g_Q2[(size_t)BATCH*NHQ*S_LEN*HDIM];
// K pair layout: idx = ((bhk*16 + ds)*2048 + s)*8 + t2   (pairs over d)
__device__ float g_K2[(size_t)BATCH*NKV*HDIM*S_LEN];
// V pair layout: idx = ((bhk*256 + kg)*128 + d)*8 + t2   (pairs over s)
__device__ float g_V2[(size_t)BATCH*NKV*S_LEN*HDIM];

// ---------------- small helpers ----------------
__device__ __forceinline__ uint32_t f2tf(float f) {
    uint32_t r; asm("cvt.rna.tf32.f32 %0, %1;" : "=r"(r) : "f"(f)); return r;
}
__device__ __forceinline__ float rtf(float f) { return __uint_as_float(f2tf(f)); }

__device__ __forceinline__ void mma_tf32(float* c, const uint32_t* a, const uint32_t* b) {
    asm volatile(
        "mma.sync.aligned.m16n8k8.row.col.f32.tf32.tf32.f32 "
        "{%0,%1,%2,%3},{%4,%5,%6,%7},{%8,%9},{%0,%1,%2,%3};"
        : "+f"(c[0]), "+f"(c[1]), "+f"(c[2]), "+f"(c[3])
        : "r"(a[0]), "r"(a[1]), "r"(a[2]), "r"(a[3]), "r"(b[0]), "r"(b[1]));
}
__device__ __forceinline__ void mma_b2(float* c, const uint32_t* a, float2 b) {
    uint32_t bb[2] = { __float_as_uint(b.x), __float_as_uint(b.y) };
    mma_tf32(c, a, bb);
}
__device__ __forceinline__ uint32_t s2u(const void* p) {
    return (uint32_t)__cvta_generic_to_shared(p);
}
__device__ __forceinline__ void cp16(uint32_t s, const void* g) {
    asm volatile("cp.async.cg.shared.global [%0], [%1], 16;" :: "r"(s), "l"(g));
}
__device__ __forceinline__ void cp_commit() { asm volatile("cp.async.commit_group;"); }
__device__ __forceinline__ void cp_wait0()  { asm volatile("cp.async.wait_group 0;"); }

#define NEG_INF __int_as_float(0xff800000)

// =====================================================================
// Prepass 1: hidden [4096 x 4096] -> A-fragment layout (rounded)
// =====================================================================
__global__ __launch_bounds__(256) void pack_A_kernel(const float* __restrict__ src,
                                                     float* __restrict__ dst) {
    __shared__ float st[16][264];
    const int tid = threadIdx.x;
    const int mb = blockIdx.y;           // 256 blocks of 16 rows
    const int k0 = blockIdx.x * 256;     // 16 blocks of 256 cols
    #pragma unroll
    for (int p = 0; p < 16; p++) {
        int j = tid + p*256;
        int row = j >> 8, col = j & 255;
        st[row][col] = src[(size_t)(mb*16 + row)*DMODEL + k0 + col];
    }
    __syncthreads();
    const int kgb = k0 >> 3;
    #pragma unroll
    for (int p = 0; p < 4; p++) {
        int jb = tid + p*256;            // chunk (lane,v0..3): 1024 chunks
        int kg_l = jb >> 5, lane = jb & 31;
        int gid = lane >> 2, tig = lane & 3;
        float4 o;
        o.x = rtf(st[gid    ][kg_l*8 + tig    ]);
        o.y = rtf(st[gid + 8][kg_l*8 + tig    ]);
        o.z = rtf(st[gid    ][kg_l*8 + tig + 4]);
        o.w = rtf(st[gid + 8][kg_l*8 + tig + 4]);
        *(float4*)(dst + ((size_t)mb*512 + kgb + kg_l)*128 + lane*4) = o;
    }
}

// =====================================================================
// Prepass 2: W [4096 x N] -> pair layout [kg][n][8] (rounded)
// order within 8: position 2*j holds k=j, 2*j+1 holds k=j+4
// =====================================================================
template<int N>
__global__ __launch_bounds__(256) void pack_W_kernel(const float* __restrict__ src,
                                                     float* __restrict__ dst) {
    __shared__ float st[8][264];
    const int tid = threadIdx.x;
    const int kg = blockIdx.y;           // 512
    const int n0 = blockIdx.x * 256;
    #pragma unroll
    for (int p = 0; p < 8; p++)
        st[p][tid] = src[(size_t)(kg*8 + p)*N + n0 + tid];
    __syncthreads();
    const int n = n0 + tid;
    float4 lo, hi;
    lo.x = rtf(st[0][tid]); lo.y = rtf(st[4][tid]);
    lo.z = rtf(st[1][tid]); lo.w = rtf(st[5][tid]);
    hi.x = rtf(st[2][tid]); hi.y = rtf(st[6][tid]);
    hi.z = rtf(st[3][tid]); hi.w = rtf(st[7][tid]);
    float* d = dst + ((size_t)kg*N + n)*8;
    *(float4*)(d)     = lo;
    *(float4*)(d + 4) = hi;
}

// =====================================================================
// GEMM: C[M,N] = A2 * W2 (both pre-rounded, fragment layouts)
// 128x128x32 tiles, 8 warps (warp tile 32x64), cp.async double buffer.
// MODE 0: scatter epilogue -> g_Q2/g_K2/g_V2 (round; scale on Q)
// MODE 1: plain epilogue -> C fp32
// =====================================================================
#define GEMM_SMEM (2*8192*4)   // 64 KB

__device__ __forceinline__ void qkv_store2(int r, int n, float val) {
    const int s = r >> 1, b = r & 1, d = n & 127;
    if (n < NHQ*HDIM) {
        const int h = n >> 7, bh = b*NHQ + h;
        const int sb = s >> 4, sl = s & 15, gq = sl & 7, rs = sl >> 3;
        const int kk = d >> 3, dl = d & 7, tq = dl & 3, cs = dl >> 2;
        const float scale = 0.08838834764831845f;  // 1/sqrt(128)
        g_Q2[((((size_t)bh*128 + sb)*16 + kk)*32 + gq*4 + tq)*4 + rs + 2*cs]
            = rtf(val * scale);
    } else if (n < (NHQ+NKV)*HDIM) {
        const int hk = (n - NHQ*HDIM) >> 7, bhk = b*NKV + hk;
        const int ds = d >> 3, dl = d & 7;
        const int t2 = (dl < 4) ? 2*dl : 2*(dl-4) + 1;
        g_K2[(((size_t)bhk*16 + ds)*S_LEN + s)*8 + t2] = rtf(val);
    } else {
        const int hk = (n - (NHQ+NKV)*HDIM) >> 7, bhk = b*NKV + hk;
        const int kg = s >> 3, sl = s & 7;
        const int t2 = (sl < 4) ? 2*sl : 2*(sl-4) + 1;
        g_V2[(((size_t)bhk*256 + kg)*HDIM + d)*8 + t2] = rtf(val);
    }
}

template<int N, int MODE>
__global__ __launch_bounds__(256, 2)
void gemm2_kernel(const float* __restrict__ A2,
                  const float* __restrict__ W2,
                  float* __restrict__ C) {
    constexpr int KT = DMODEL / 32;   // 128 k-tiles

    extern __shared__ float sm[];
    float* As = sm;            // [2][4096]
    float* Bs = sm + 8192;     // [2][4096]

    const int tid  = threadIdx.x;
    const int wid  = tid >> 5, lane = tid & 31;
    const int gid  = lane >> 2, tig = lane & 3;
    const int wrow = wid >> 1, wcol = wid & 1;
    const int bn   = blockIdx.x, bm = blockIdx.y;

    auto loadA = [&](int buf, int kt) {
        float* dst = As + buf*4096;
        #pragma unroll
        for (int p = 0; p < 4; p++) {
            int j = tid + p*256;
            int mbl = j >> 7, kgl = (j >> 5) & 3, ln = j & 31;
            cp16(s2u(dst + j*4),
                 A2 + (((size_t)(bm*8 + mbl)*KG_ALL + kt*4 + kgl)*32 + ln)*4);
        }
    };
    auto loadB = [&](int buf, int kt) {
        float* dst = Bs + buf*4096;
        #pragma unroll
        for (int p = 0; p < 4; p++) {
            int j = tid + p*256;
            int kgl = j >> 8, r = j & 255, nl = r >> 1, half = r & 1;
            cp16(s2u(dst + kgl*1024 + nl*8 + half*4),
                 W2 + ((size_t)(kt*4 + kgl)*N + bn*128 + nl)*8 + half*4);
        }
    };

    float acc[2][8][4];
    #pragma unroll
    for (int mf = 0; mf < 2; mf++)
        #pragma unroll
        for (int nf = 0; nf < 8; nf++)
            #pragma unroll
            for (int i = 0; i < 4; i++) acc[mf][nf][i] = 0.f;

    loadA(0, 0); loadB(0, 0); cp_commit();

    for (int kt = 0; kt < KT; kt++) {
        cp_wait0();
        __syncthreads();
        if (kt + 1 < KT) {
            loadA((kt+1)&1, kt+1);
            loadB((kt+1)&1, kt+1);
            cp_commit();
        }
        const float4* a4 = (const float4*)(As + (kt&1)*4096);
        const float2* b2 = (const float2*)(Bs + (kt&1)*4096);

        #pragma unroll
        for (int ks = 0; ks < 4; ks++) {
            uint32_t af[2][4];
            #pragma unroll
            for (int mf = 0; mf < 2; mf++) {
                float4 av = a4[((wrow*2 + mf)*4 + ks)*32 + lane];
                af[mf][0] = __float_as_uint(av.x);
                af[mf][1] = __float_as_uint(av.y);
                af[mf][2] = __float_as_uint(av.z);
                af[mf][3] = __float_as_uint(av.w);
            }
            #pragma unroll
            for (int nf = 0; nf < 8; nf++) {
                float2 bv = b2[(ks*128 + wcol*64 + nf*8 + gid)*4 + tig];
                mma_b2(acc[0][nf], af[0], bv);
                mma_b2(acc[1][nf], af[1], bv);
            }
        }
        __syncthreads();
    }

    #pragma unroll
    for (int mf = 0; mf < 2; mf++) {
        #pragma unroll
        for (int nf = 0; nf < 8; nf++) {
            int r = bm*128 + wrow*32 + mf*16 + gid;
            int c = bn*128 + wcol*64 + nf*8 + tig*2;
            float v0 = acc[mf][nf][0], v1 = acc[mf][nf][1];
            float v2 = acc[mf][nf][2], v3 = acc[mf][nf][3];
            if (MODE == 1) {
                C[(size_t)r*N + c]         = v0;
                C[(size_t)r*N + c + 1]     = v1;
                C[(size_t)(r+8)*N + c]     = v2;
                C[(size_t)(r+8)*N + c + 1] = v3;
            } else {
                qkv_store2(r,   c,   v0);
                qkv_store2(r,   c+1, v1);
                qkv_store2(r+8, c,   v2);
                qkv_store2(r+8, c+1, v3);
            }
        }
    }
}

// =====================================================================
// Flash attention: block = (qtile 128, head h, batch b), 8 warps x 16 rows.
// K tile: [ds 16][kvl 64][8] pairs over d; V tile: [kgl 8][d 128][8] pairs over s.
// All operands pre-rounded tf32 -> zero cvt in loops; B frags are LDS.64.
// =====================================================================
#define BKV 64
#define ATTN_SMEM (2*(8192 + 8192)*4)   // 128 KB

__global__ __launch_bounds__(256, 1)
void attn_kernel() {
    extern __shared__ float sm[];
    float* Ks = sm;            // [2][8192]
    float* Vs = sm + 16384;    // [2][8192]

    const int tid = threadIdx.x;
    const int wid = tid >> 5, lane = tid & 31;
    const int gid = lane >> 2, tig = lane & 3;
    const int qt = blockIdx.x, h = blockIdx.y, b = blockIdx.z;
    const int hk = h >> 2;
    const int bh = b*NHQ + h, bhk = b*NKV + hk;

    // ---- Q fragments: 16 coalesced LDG.128 (pre-scaled, pre-rounded) ----
    const int sb = qt*8 + wid;
    const float4* q4 = (const float4*)g_Q2 + ((size_t)bh*128 + sb)*16*32 + lane;
    uint32_t qa[16][4];
    #pragma unroll
    for (int kk = 0; kk < 16; kk++) {
        float4 qv = q4[kk*32];
        qa[kk][0] = __float_as_uint(qv.x);
        qa[kk][1] = __float_as_uint(qv.y);
        qa[kk][2] = __float_as_uint(qv.z);
        qa[kk][3] = __float_as_uint(qv.w);
    }

    const float* Kg = g_K2 + (size_t)bhk*16*S_LEN*8;
    const float* Vg = g_V2 + (size_t)bhk*256*HDIM*8;

    auto loadKV = [&](int buf, int it) {
        float* kd = Ks + buf*8192;
        #pragma unroll
        for (int p = 0; p < 8; p++) {
            int j = tid + p*256;
            int ds = j >> 7, r = j & 127, kvl = r >> 1, half = r & 1;
            cp16(s2u(kd + ds*512 + kvl*8 + half*4),
                 Kg + ((size_t)ds*S_LEN + it*BKV + kvl)*8 + half*4);
        }
        float* vd = Vs + buf*8192;
        #pragma unroll
        for (int p = 0; p < 8; p++) {
            int j = tid + p*256;
            int kgl = j >> 8, r = j & 255, d = r >> 1, half = r & 1;
            cp16(s2u(vd + kgl*1024 + d*8 + half*4),
                 Vg + ((size_t)(it*8 + kgl)*HDIM + d)*8 + half*4);
        }
    };

    float m0 = NEG_INF, m1 = NEG_INF, l0 = 0.f, l1 = 0.f;
    float o[16][4];
    #pragma unroll
    for (int jn = 0; jn < 16; jn++)
        #pragma unroll
        for (int i = 0; i < 4; i++) o[jn][i] = 0.f;

    loadKV(0, 0); cp_commit();

    const int NIT = S_LEN / BKV;   // 32
    for (int it = 0; it < NIT; it++) {
        cp_wait0();
        __syncthreads();
        if (it + 1 < NIT) { loadKV((it+1)&1, it+1); cp_commit(); }

        const float2* kbuf = (const float2*)(Ks + (it&1)*8192);
        const float2* vbuf = (const float2*)(Vs + (it&1)*8192);

        // ---- S = Q K^T : 16 x 64 per warp ----
        float sc[8][4];
        #pragma unroll
        for (int jn = 0; jn < 8; jn++)
            #pragma unroll
            for (int i = 0; i < 4; i++) sc[jn][i] = 0.f;

        #pragma unroll
        for (int ks = 0; ks < 16; ks++) {
            #pragma unroll
            for (int jn = 0; jn < 8; jn++) {
                float2 kv = kbuf[(ks*64 + jn*8 + gid)*4 + tig];
                mma_b2(sc[jn], qa[ks], kv);
            }
        }

        // ---- online softmax (rows gid, gid+8; quad-local reductions) ----
        float rmax0 = NEG_INF, rmax1 = NEG_INF;
        #pragma unroll
        for (int jn = 0; jn < 8; jn++) {
            rmax0 = fmaxf(rmax0, fmaxf(sc[jn][0], sc[jn][1]));
            rmax1 = fmaxf(rmax1, fmaxf(sc[jn][2], sc[jn][3]));
        }
        rmax0 = fmaxf(rmax0, __shfl_xor_sync(0xffffffffu, rmax0, 1));
        rmax0 = fmaxf(rmax0, __shfl_xor_sync(0xffffffffu, rmax0, 2));
        rmax1 = fmaxf(rmax1, __shfl_xor_sync(0xffffffffu, rmax1, 1));
        rmax1 = fmaxf(rmax1, __shfl_xor_sync(0xffffffffu, rmax1, 2));

        float mn0 = fmaxf(m0, rmax0), mn1 = fmaxf(m1, rmax1);
        float al0 = __expf(m0 - mn0), al1 = __expf(m1 - mn1);

        float rs0 = 0.f, rs1 = 0.f;
        #pragma unroll
        for (int jn = 0; jn < 8; jn++) {
            sc[jn][0] = rtf(__expf(sc[jn][0] - mn0));
            sc[jn][1] = rtf(__expf(sc[jn][1] - mn0));
            sc[jn][2] = rtf(__expf(sc[jn][2] - mn1));
            sc[jn][3] = rtf(__expf(sc[jn][3] - mn1));
            rs0 += sc[jn][0] + sc[jn][1];
            rs1 += sc[jn][2] + sc[jn][3];
        }
        rs0 += __shfl_xor_sync(0xffffffffu, rs0, 1);
        rs0 += __shfl_xor_sync(0xffffffffu, rs0, 2);
        rs1 += __shfl_xor_sync(0xffffffffu, rs1, 1);
        rs1 += __shfl_xor_sync(0xffffffffu, rs1, 2);

        l0 = l0*al0 + rs0;  l1 = l1*al1 + rs1;
        m0 = mn0;           m1 = mn1;

        #pragma unroll
        for (int jn = 0; jn < 16; jn++) {
            o[jn][0] *= al0; o[jn][1] *= al0;
            o[jn][2] *= al1; o[jn][3] *= al1;
        }

        // ---- O += P V : P C-layout -> A-layout via quad shuffles ----
        #pragma unroll
        for (int ks = 0; ks < 8; ks++) {
            int srcA = (lane & 28) + (tig >> 1);
            int srcB = srcA + 2;
            float xa0 = __shfl_sync(0xffffffffu, sc[ks][0], srcA);
            float ya0 = __shfl_sync(0xffffffffu, sc[ks][1], srcA);
            float xa2 = __shfl_sync(0xffffffffu, sc[ks][2], srcA);
            float ya2 = __shfl_sync(0xffffffffu, sc[ks][3], srcA);
            float xb0 = __shfl_sync(0xffffffffu, sc[ks][0], srcB);
            float yb0 = __shfl_sync(0xffffffffu, sc[ks][1], srcB);
            float xb2 = __shfl_sync(0xffffffffu, sc[ks][2], srcB);
            float yb2 = __shfl_sync(0xffffffffu, sc[ks][3], srcB);
            bool odd = (tig & 1);
            uint32_t pa[4];
            pa[0] = __float_as_uint(odd ? ya0 : xa0);   // (row gid,   k=tig)
            pa[1] = __float_as_uint(odd ? ya2 : xa2);   // (row gid+8, k=tig)
            pa[2] = __float_as_uint(odd ? yb0 : xb0);   // (row gid,   k=tig+4)
            pa[3] = __float_as_uint(odd ? yb2 : xb2);   // (row gid+8, k=tig+4)

            #pragma unroll
            for (int jn = 0; jn < 16; jn++) {
                float2 vv = vbuf[(ks*128 + jn*8 + gid)*4 + tig];
                mma_b2(o[jn], pa, vv);
            }
        }
    }

    // ---- epilogue: scatter (rounded) into g_attn2 A-fragment layout ----
    float il0 = 1.f / l0, il1 = 1.f / l1;
    const int s0 = qt*128 + wid*16 + gid;
    #pragma unroll
    for (int jn = 0; jn < 16; jn++) {
        int c0 = h*HDIM + jn*8 + tig*2;
        float vals[4] = { o[jn][0]*il0, o[jn][1]*il0, o[jn][2]*il1, o[jn][3]*il1 };
        #pragma unroll
        for (int i = 0; i < 4; i++) {
            int s = s0 + (i >> 1)*8;
            int k = c0 + (i & 1);
            int m = 2*s + b;
            int mb = m >> 4, ml = m & 15, gA = ml & 7, rs = ml >> 3;
            int kg = k >> 3, kl = k & 7, tA = kl & 3, cs = kl >> 2;
            g_attn2[(((size_t)mb*KG_ALL + kg)*32 + gA*4 + tA)*4 + rs + 2*cs]
                = rtf(vals[i]);
        }
    }
}

// =====================================================================
// launcher
// =====================================================================
extern "C" void kernel_launch(void* const* d_in, const int* in_sizes, int n_in,
                              void* d_out, int out_size) {
    const float* hidden = (const float*)d_in[0];
    const float* w_qkv  = (const float*)d_in[1];
    const float* w_o    = (const float*)d_in[2];
    float* out = (float*)d_out;

    cudaFuncSetAttribute(gemm2_kernel<N_QKV,0>,
                         cudaFuncAttributeMaxDynamicSharedMemorySize, GEMM_SMEM);
    cudaFuncSetAttribute(gemm2_kernel<DMODEL,1>,
                         cudaFuncAttributeMaxDynamicSharedMemorySize, GEMM_SMEM);
    cudaFuncSetAttribute(attn_kernel,
                         cudaFuncAttributeMaxDynamicSharedMemorySize, ATTN_SMEM);

    float* hid2;  cudaGetSymbolAddress((void**)&hid2,  g_hid2);
    float* wq2;   cudaGetSymbolAddress((void**)&wq2,   g_Wq2);
    float* wo2;   cudaGetSymbolAddress((void**)&wo2,   g_Wo2);
    float* at2;   cudaGetSymbolAddress((void**)&at2,   g_attn2);

    // 0) prepasses: round-to-tf32 + permute into fragment-native layouts
    pack_A_kernel<<<dim3(16, 256), 256>>>(hidden, hid2);
    pack_W_kernel<N_QKV><<<dim3(N_QKV/256, KG_ALL), 256>>>(w_qkv, wq2);
    pack_W_kernel<DMODEL><<<dim3(DMODEL/256, KG_ALL), 256>>>(w_o, wo2);

    // 1) fused QKV projection, scatter epilogue -> Q2/K2/V2
    gemm2_kernel<N_QKV,0><<<dim3(N_QKV/128, MROWS/128), 256, GEMM_SMEM>>>(hid2, wq2, nullptr);

    // 2) flash attention (full softmax == ring online-softmax)
    attn_kernel<<<dim3(S_LEN/128, NHQ, BATCH), 256, ATTN_SMEM>>>();

    // 3) output projection
    gemm2_kernel<DMODEL,1><<<dim3(DMODEL/128, MROWS/128), 256, GEMM_SMEM>>>(at2, wo2, out);
}